// round 1
// baseline (speedup 1.0000x reference)
#include <cuda_runtime.h>
#include <cstdint>

#define MAX_ATOMS 40000
#define MAX_EDGES 640000
#define NFM 128

// Scratch (no allocation allowed in kernel_launch)
__device__ float g_f[(size_t)MAX_ATOMS * NFM];     // f = x @ W_in
__device__ float g_conv[(size_t)MAX_ATOMS * NFM];  // segment-summed conv
__device__ int   g_rowstart[MAX_ATOMS + 1];        // CSR offsets from sorted seg_i

// ---------------------------------------------------------------------------
// GEMM: C[M,128] = A[M,128] @ B[128,128] (+ bias). BM=128, BN=128, BK=32.
// 256 threads, each computes an 8x8 micro-tile. A staged transposed in smem.
// ---------------------------------------------------------------------------
__global__ __launch_bounds__(256, 2)
void gemm128_kernel(const float* __restrict__ A, const float* __restrict__ B,
                    const float* __restrict__ bias, float* __restrict__ C, int M)
{
    __shared__ float As[32][132];   // k-major (transposed), padded stride 132
    __shared__ float Bs[32][128];   // k-major, natural

    const int tid = threadIdx.x;
    const int m0  = blockIdx.x * 128;
    const int tx  = tid & 15;       // 0..15
    const int ty  = tid >> 4;       // 0..15
    const int row0 = ty * 8;
    const int col0 = tx * 8;

    float acc[8][8];
#pragma unroll
    for (int i = 0; i < 8; i++)
#pragma unroll
        for (int j = 0; j < 8; j++) acc[i][j] = 0.0f;

    for (int kb = 0; kb < 128; kb += 32) {
        // --- load A chunk: 128 rows x 32 cols -> As[k][m] (transposed) ---
#pragma unroll
        for (int it = 0; it < 4; it++) {
            int idx  = tid + it * 256;       // 0..1023
            int row  = idx >> 3;             // 0..127
            int f4c  = idx & 7;              // 0..7 -> k-local = f4c*4..+3
            int m    = m0 + row;
            float4 v = make_float4(0.f, 0.f, 0.f, 0.f);
            if (m < M)
                v = *reinterpret_cast<const float4*>(&A[(size_t)m * 128 + kb + f4c * 4]);
            int kk = f4c * 4;
            As[kk + 0][row] = v.x;
            As[kk + 1][row] = v.y;
            As[kk + 2][row] = v.z;
            As[kk + 3][row] = v.w;
        }
        // --- load B chunk: 32 rows x 128 cols ---
#pragma unroll
        for (int it = 0; it < 4; it++) {
            int idx = tid + it * 256;        // 0..1023
            int kl  = idx >> 5;              // 0..31
            int c4  = idx & 31;              // 0..31
            float4 v = *reinterpret_cast<const float4*>(&B[(size_t)(kb + kl) * 128 + c4 * 4]);
            *reinterpret_cast<float4*>(&Bs[kl][c4 * 4]) = v;
        }
        __syncthreads();

#pragma unroll
        for (int k = 0; k < 32; k++) {
            float4 a0 = *reinterpret_cast<const float4*>(&As[k][row0]);
            float4 a1 = *reinterpret_cast<const float4*>(&As[k][row0 + 4]);
            float4 b0 = *reinterpret_cast<const float4*>(&Bs[k][col0]);
            float4 b1 = *reinterpret_cast<const float4*>(&Bs[k][col0 + 4]);
            float a[8] = {a0.x, a0.y, a0.z, a0.w, a1.x, a1.y, a1.z, a1.w};
            float b[8] = {b0.x, b0.y, b0.z, b0.w, b1.x, b1.y, b1.z, b1.w};
#pragma unroll
            for (int i = 0; i < 8; i++)
#pragma unroll
                for (int j = 0; j < 8; j++)
                    acc[i][j] = fmaf(a[i], b[j], acc[i][j]);
        }
        __syncthreads();
    }

    // epilogue
    float bv[8];
#pragma unroll
    for (int j = 0; j < 8; j++) bv[j] = bias ? bias[col0 + j] : 0.0f;

#pragma unroll
    for (int i = 0; i < 8; i++) {
        int m = m0 + row0 + i;
        if (m < M) {
            float4 o0 = make_float4(acc[i][0] + bv[0], acc[i][1] + bv[1],
                                    acc[i][2] + bv[2], acc[i][3] + bv[3]);
            float4 o1 = make_float4(acc[i][4] + bv[4], acc[i][5] + bv[5],
                                    acc[i][6] + bv[6], acc[i][7] + bv[7]);
            *reinterpret_cast<float4*>(&C[(size_t)m * 128 + col0])     = o0;
            *reinterpret_cast<float4*>(&C[(size_t)m * 128 + col0 + 4]) = o1;
        }
    }
}

// ---------------------------------------------------------------------------
// CSR offsets from sorted seg_i: row_start[a] = lower_bound(seg_i, a)
// ---------------------------------------------------------------------------
__global__ void offsets_kernel(const int* __restrict__ seg_i, int num_edges, int num_atoms)
{
    int a = blockIdx.x * blockDim.x + threadIdx.x;
    if (a > num_atoms) return;
    int lo = 0, hi = num_edges;
    while (lo < hi) {
        int mid = (lo + hi) >> 1;
        if (seg_i[mid] < a) lo = mid + 1; else hi = mid;
    }
    g_rowstart[a] = lo;
}

// ---------------------------------------------------------------------------
// Edge kernel: conv[a,:] = sum_{k in [row_start[a],row_start[a+1])} w_ij[k,:] * f[idx_j[k],:]
// One warp per atom; each lane owns 4 channels (float4).
// ---------------------------------------------------------------------------
__global__ __launch_bounds__(128)
void conv_kernel(const float* __restrict__ w_ij, const int* __restrict__ idx_j,
                 int num_atoms)
{
    const int warp = threadIdx.x >> 5;
    const int lane = threadIdx.x & 31;
    const int a = blockIdx.x * 4 + warp;
    if (a >= num_atoms) return;

    const int s = g_rowstart[a];
    const int e = g_rowstart[a + 1];
    const int c = lane * 4;

    float4 acc = make_float4(0.f, 0.f, 0.f, 0.f);

    int k = s;
    // unroll-by-2 for memory-level parallelism
    for (; k + 1 < e; k += 2) {
        int j0 = __ldg(&idx_j[k]);
        int j1 = __ldg(&idx_j[k + 1]);
        float4 w0 = *reinterpret_cast<const float4*>(&w_ij[(size_t)k * 128 + c]);
        float4 w1 = *reinterpret_cast<const float4*>(&w_ij[(size_t)(k + 1) * 128 + c]);
        float4 f0 = *reinterpret_cast<const float4*>(&g_f[(size_t)j0 * 128 + c]);
        float4 f1 = *reinterpret_cast<const float4*>(&g_f[(size_t)j1 * 128 + c]);
        acc.x = fmaf(w0.x, f0.x, acc.x); acc.y = fmaf(w0.y, f0.y, acc.y);
        acc.z = fmaf(w0.z, f0.z, acc.z); acc.w = fmaf(w0.w, f0.w, acc.w);
        acc.x = fmaf(w1.x, f1.x, acc.x); acc.y = fmaf(w1.y, f1.y, acc.y);
        acc.z = fmaf(w1.z, f1.z, acc.z); acc.w = fmaf(w1.w, f1.w, acc.w);
    }
    if (k < e) {
        int j0 = __ldg(&idx_j[k]);
        float4 w0 = *reinterpret_cast<const float4*>(&w_ij[(size_t)k * 128 + c]);
        float4 f0 = *reinterpret_cast<const float4*>(&g_f[(size_t)j0 * 128 + c]);
        acc.x = fmaf(w0.x, f0.x, acc.x); acc.y = fmaf(w0.y, f0.y, acc.y);
        acc.z = fmaf(w0.z, f0.z, acc.z); acc.w = fmaf(w0.w, f0.w, acc.w);
    }

    *reinterpret_cast<float4*>(&g_conv[(size_t)a * 128 + c]) = acc;
}

// ---------------------------------------------------------------------------
extern "C" void kernel_launch(void* const* d_in, const int* in_sizes, int n_in,
                              void* d_out, int out_size)
{
    // metadata order: x, w_ij, seg_i, idx_j, [seg_i_sum], W_in, W_out, b_out
    const float* x    = (const float*)d_in[0];
    const float* wij  = (const float*)d_in[1];
    const int*   seg  = (const int*)d_in[2];
    const int*   idxj = (const int*)d_in[3];
    int base = 4;
    if (n_in >= 8 && in_sizes[4] == 1) base = 5;   // skip scalar seg_i_sum
    const float* Win  = (const float*)d_in[base];
    const float* Wout = (const float*)d_in[base + 1];
    const float* bout = (const float*)d_in[base + 2];

    int num_edges = in_sizes[2];
    int num_atoms = out_size / NFM;
    if (num_atoms > MAX_ATOMS) num_atoms = MAX_ATOMS;
    if (num_edges > MAX_EDGES) num_edges = MAX_EDGES;

    float* f_ptr    = nullptr;
    float* conv_ptr = nullptr;
    cudaGetSymbolAddress((void**)&f_ptr, g_f);
    cudaGetSymbolAddress((void**)&conv_ptr, g_conv);

    // 1) f = x @ W_in
    int gblocks = (num_atoms + 127) / 128;
    gemm128_kernel<<<gblocks, 256>>>(x, Win, nullptr, f_ptr, num_atoms);

    // 2) CSR offsets from sorted seg_i
    offsets_kernel<<<(num_atoms + 1 + 255) / 256, 256>>>(seg, num_edges, num_atoms);

    // 3) conv = segment_sum(w_ij * f[idx_j])
    conv_kernel<<<(num_atoms + 3) / 4, 128>>>(wij, idxj, num_atoms);

    // 4) out = conv @ W_out + b_out
    gemm128_kernel<<<gblocks, 256>>>(conv_ptr, Wout, bout, (float*)d_out, num_atoms);
}

// round 3
// speedup vs baseline: 1.2951x; 1.2951x over previous
#include <cuda_runtime.h>
#include <cuda_bf16.h>
#include <cstdint>

#define MAX_ATOMS 40000
#define MAX_EDGES 640000
#define NFM 128

// ---------------------------------------------------------------------------
// Scratch (no allocation allowed anywhere)
// ---------------------------------------------------------------------------
__device__ float    g_f[(size_t)MAX_ATOMS * NFM];     // f = x @ W_in
__device__ float    g_conv[(size_t)MAX_ATOMS * NFM];  // segment-summed conv
__device__ int      g_rowstart[MAX_ATOMS + 1];        // CSR offsets
// Pre-packed B fragments in mma.m16n8k16 register order.
// [matrix: 0=Win 1=Wout][term: 0=hi 1=lo][ ((t*8+k)*32+lane)*2 + reg ]
__device__ uint32_t g_Bfrag[2][2][8192];

// ---------------------------------------------------------------------------
// bf16 split helpers
// ---------------------------------------------------------------------------
__device__ __forceinline__ void split_pair(float v0, float v1,
                                           uint32_t& hp, uint32_t& lp) {
    __nv_bfloat16 h0 = __float2bfloat16(v0);
    __nv_bfloat16 h1 = __float2bfloat16(v1);
    __nv_bfloat16 l0 = __float2bfloat16(v0 - __bfloat162float(h0));
    __nv_bfloat16 l1 = __float2bfloat16(v1 - __bfloat162float(h1));
    hp = (uint32_t)__bfloat16_as_ushort(h0) | ((uint32_t)__bfloat16_as_ushort(h1) << 16);
    lp = (uint32_t)__bfloat16_as_ushort(l0) | ((uint32_t)__bfloat16_as_ushort(l1) << 16);
}

// mma.sync m16n8k16 row.col f32.bf16.bf16.f32
__device__ __forceinline__ void mma16816(float* c, const uint32_t* a,
                                         uint32_t b0, uint32_t b1) {
    asm volatile(
        "mma.sync.aligned.m16n8k16.row.col.f32.bf16.bf16.f32 "
        "{%0,%1,%2,%3}, {%4,%5,%6,%7}, {%8,%9}, {%0,%1,%2,%3};"
        : "+f"(c[0]), "+f"(c[1]), "+f"(c[2]), "+f"(c[3])
        : "r"(a[0]), "r"(a[1]), "r"(a[2]), "r"(a[3]), "r"(b0), "r"(b1));
}

// ---------------------------------------------------------------------------
// Prep: pack both weight matrices into B-fragment order, split hi/lo.
// W is [K=128, N=128] row-major fp32. Fragment (t,k,lane,reg):
//   b0: B[k*16 + (lane&3)*2 + reg*8    ][t*8 + lane>>2]
//   b1: B[k*16 + (lane&3)*2 + reg*8 + 1][t*8 + lane>>2]
// ---------------------------------------------------------------------------
__global__ void prep_weights_kernel(const float* __restrict__ W_in,
                                    const float* __restrict__ W_out)
{
    int id = blockIdx.x * blockDim.x + threadIdx.x;   // 0..32767
    int reg  = id & 1;
    int lane = (id >> 1) & 31;
    int k    = (id >> 6) & 7;
    int t    = (id >> 9) & 15;
    int term = (id >> 13) & 1;
    int mat  = (id >> 14) & 1;

    const float* W = mat ? W_out : W_in;
    int kr = k * 16 + (lane & 3) * 2 + reg * 8;
    int n  = t * 8 + (lane >> 2);
    float v0 = W[(size_t)kr * 128 + n];
    float v1 = W[(size_t)(kr + 1) * 128 + n];
    uint32_t hp, lp;
    split_pair(v0, v1, hp, lp);
    g_Bfrag[mat][term][(((t * 8 + k) * 32) + lane) * 2 + reg] = term ? lp : hp;
}

// ---------------------------------------------------------------------------
// Tensor-core GEMM via mma.sync: C[M,128] = A[M,128] @ W[128,128] (+bias).
// Split bf16 3-term. CTA: 128x128 tile, 8 warps (warp tile 32x64).
// ---------------------------------------------------------------------------
#define A_STRIDE 136   // bf16 elems per row (padded)

__global__ __launch_bounds__(256, 1)
void gemm_mma_kernel(const float* __restrict__ A,
                     const uint32_t* __restrict__ Bh,
                     const uint32_t* __restrict__ Bl,
                     const float* __restrict__ bias,
                     float* __restrict__ C, int M)
{
    extern __shared__ __nv_bfloat16 sA[];     // [2][128][A_STRIDE]
    __nv_bfloat16* Ah = sA;
    __nv_bfloat16* Al = sA + 128 * A_STRIDE;

    const int tid = threadIdx.x;
    const int m0  = blockIdx.x * 128;

    // ---- stage A tile: fp32 -> hi/lo bf16 in smem ----
#pragma unroll
    for (int it = 0; it < 32; it++) {
        int p  = tid + it * 256;              // 0..8191 pairs
        int m  = p >> 6;                      // local row
        int kp = (p & 63) << 1;               // even col
        float2 v = make_float2(0.f, 0.f);
        if (m0 + m < M)
            v = *reinterpret_cast<const float2*>(&A[(size_t)(m0 + m) * 128 + kp]);
        uint32_t hp, lp;
        split_pair(v.x, v.y, hp, lp);
        *reinterpret_cast<uint32_t*>(&Ah[m * A_STRIDE + kp]) = hp;
        *reinterpret_cast<uint32_t*>(&Al[m * A_STRIDE + kp]) = lp;
    }
    __syncthreads();

    const int wid  = tid >> 5;
    const int lane = tid & 31;
    const int wm   = wid & 3;                 // M slice (32 rows)
    const int wn   = wid >> 2;                // N half (64 cols)
    const int g    = lane >> 2;               // group id 0..7
    const int tg   = lane & 3;                // thread-in-group 0..3

    float acc[2][8][4];
#pragma unroll
    for (int mf = 0; mf < 2; mf++)
#pragma unroll
        for (int t8 = 0; t8 < 8; t8++)
#pragma unroll
            for (int i = 0; i < 4; i++) acc[mf][t8][i] = 0.f;

#pragma unroll
    for (int k = 0; k < 8; k++) {
        uint32_t ah[2][4], al[2][4];
        const int cb = k * 16 + tg * 2;       // col base within K
#pragma unroll
        for (int mf = 0; mf < 2; mf++) {
            int r = wm * 32 + mf * 16 + g;
            ah[mf][0] = *reinterpret_cast<const uint32_t*>(&Ah[r * A_STRIDE + cb]);
            ah[mf][1] = *reinterpret_cast<const uint32_t*>(&Ah[(r + 8) * A_STRIDE + cb]);
            ah[mf][2] = *reinterpret_cast<const uint32_t*>(&Ah[r * A_STRIDE + cb + 8]);
            ah[mf][3] = *reinterpret_cast<const uint32_t*>(&Ah[(r + 8) * A_STRIDE + cb + 8]);
            al[mf][0] = *reinterpret_cast<const uint32_t*>(&Al[r * A_STRIDE + cb]);
            al[mf][1] = *reinterpret_cast<const uint32_t*>(&Al[(r + 8) * A_STRIDE + cb]);
            al[mf][2] = *reinterpret_cast<const uint32_t*>(&Al[r * A_STRIDE + cb + 8]);
            al[mf][3] = *reinterpret_cast<const uint32_t*>(&Al[(r + 8) * A_STRIDE + cb + 8]);
        }
#pragma unroll
        for (int t8 = 0; t8 < 8; t8++) {
            int fidx = (((wn * 8 + t8) * 8 + k) * 32 + lane) * 2;
            uint32_t bh0 = __ldg(&Bh[fidx]);
            uint32_t bh1 = __ldg(&Bh[fidx + 1]);
            uint32_t bl0 = __ldg(&Bl[fidx]);
            uint32_t bl1 = __ldg(&Bl[fidx + 1]);
#pragma unroll
            for (int mf = 0; mf < 2; mf++) {
                mma16816(acc[mf][t8], ah[mf], bh0, bh1);   // Ah*Bh
                mma16816(acc[mf][t8], ah[mf], bl0, bl1);   // Ah*Bl
                mma16816(acc[mf][t8], al[mf], bh0, bh1);   // Al*Bh
            }
        }
    }

    // ---- epilogue ----
#pragma unroll
    for (int t8 = 0; t8 < 8; t8++) {
        int col = wn * 64 + t8 * 8 + tg * 2;
        float b0 = bias ? __ldg(&bias[col])     : 0.f;
        float b1 = bias ? __ldg(&bias[col + 1]) : 0.f;
#pragma unroll
        for (int mf = 0; mf < 2; mf++) {
            int row = m0 + wm * 32 + mf * 16 + g;
            if (row < M) {
                float2 o0 = make_float2(acc[mf][t8][0] + b0, acc[mf][t8][1] + b1);
                *reinterpret_cast<float2*>(&C[(size_t)row * 128 + col]) = o0;
            }
            if (row + 8 < M) {
                float2 o1 = make_float2(acc[mf][t8][2] + b0, acc[mf][t8][3] + b1);
                *reinterpret_cast<float2*>(&C[(size_t)(row + 8) * 128 + col]) = o1;
            }
        }
    }
}

// ---------------------------------------------------------------------------
// CSR offsets from sorted seg_i: row_start[a] = lower_bound(seg_i, a)
// ---------------------------------------------------------------------------
__global__ void offsets_kernel(const int* __restrict__ seg_i, int num_edges, int num_atoms)
{
    int a = blockIdx.x * blockDim.x + threadIdx.x;
    if (a > num_atoms) return;
    int lo = 0, hi = num_edges;
    while (lo < hi) {
        int mid = (lo + hi) >> 1;
        if (seg_i[mid] < a) lo = mid + 1; else hi = mid;
    }
    g_rowstart[a] = lo;
}

// ---------------------------------------------------------------------------
// Edge kernel (unchanged): one warp per atom, lane owns 4 channels.
// ---------------------------------------------------------------------------
__global__ __launch_bounds__(128)
void conv_kernel(const float* __restrict__ w_ij, const int* __restrict__ idx_j,
                 int num_atoms)
{
    const int warp = threadIdx.x >> 5;
    const int lane = threadIdx.x & 31;
    const int a = blockIdx.x * 4 + warp;
    if (a >= num_atoms) return;

    const int s = g_rowstart[a];
    const int e = g_rowstart[a + 1];
    const int c = lane * 4;

    float4 acc = make_float4(0.f, 0.f, 0.f, 0.f);

    int k = s;
    for (; k + 1 < e; k += 2) {
        int j0 = __ldg(&idx_j[k]);
        int j1 = __ldg(&idx_j[k + 1]);
        float4 w0 = *reinterpret_cast<const float4*>(&w_ij[(size_t)k * 128 + c]);
        float4 w1 = *reinterpret_cast<const float4*>(&w_ij[(size_t)(k + 1) * 128 + c]);
        float4 f0 = *reinterpret_cast<const float4*>(&g_f[(size_t)j0 * 128 + c]);
        float4 f1 = *reinterpret_cast<const float4*>(&g_f[(size_t)j1 * 128 + c]);
        acc.x = fmaf(w0.x, f0.x, acc.x); acc.y = fmaf(w0.y, f0.y, acc.y);
        acc.z = fmaf(w0.z, f0.z, acc.z); acc.w = fmaf(w0.w, f0.w, acc.w);
        acc.x = fmaf(w1.x, f1.x, acc.x); acc.y = fmaf(w1.y, f1.y, acc.y);
        acc.z = fmaf(w1.z, f1.z, acc.z); acc.w = fmaf(w1.w, f1.w, acc.w);
    }
    if (k < e) {
        int j0 = __ldg(&idx_j[k]);
        float4 w0 = *reinterpret_cast<const float4*>(&w_ij[(size_t)k * 128 + c]);
        float4 f0 = *reinterpret_cast<const float4*>(&g_f[(size_t)j0 * 128 + c]);
        acc.x = fmaf(w0.x, f0.x, acc.x); acc.y = fmaf(w0.y, f0.y, acc.y);
        acc.z = fmaf(w0.z, f0.z, acc.z); acc.w = fmaf(w0.w, f0.w, acc.w);
    }

    *reinterpret_cast<float4*>(&g_conv[(size_t)a * 128 + c]) = acc;
}

// ---------------------------------------------------------------------------
extern "C" void kernel_launch(void* const* d_in, const int* in_sizes, int n_in,
                              void* d_out, int out_size)
{
    const float* x    = (const float*)d_in[0];
    const float* wij  = (const float*)d_in[1];
    const int*   seg  = (const int*)d_in[2];
    const int*   idxj = (const int*)d_in[3];
    int base = 4;
    if (n_in >= 8 && in_sizes[4] == 1) base = 5;   // skip scalar seg_i_sum
    const float* Win  = (const float*)d_in[base];
    const float* Wout = (const float*)d_in[base + 1];
    const float* bout = (const float*)d_in[base + 2];

    int num_edges = in_sizes[2];
    int num_atoms = out_size / NFM;
    if (num_atoms > MAX_ATOMS) num_atoms = MAX_ATOMS;
    if (num_edges > MAX_EDGES) num_edges = MAX_EDGES;

    float*    f_ptr    = nullptr;
    float*    conv_ptr = nullptr;
    uint32_t* bfrag    = nullptr;
    cudaGetSymbolAddress((void**)&f_ptr, g_f);
    cudaGetSymbolAddress((void**)&conv_ptr, g_conv);
    cudaGetSymbolAddress((void**)&bfrag, g_Bfrag);

    const int SMEM_A = 2 * 128 * A_STRIDE * (int)sizeof(__nv_bfloat16);  // 69632
    cudaFuncSetAttribute(gemm_mma_kernel,
                         cudaFuncAttributeMaxDynamicSharedMemorySize, SMEM_A);

    int gblocks = (num_atoms + 127) / 128;

    // 0) pack weights into mma B fragments (hi/lo)
    prep_weights_kernel<<<128, 256>>>(Win, Wout);

    // 1) f = x @ W_in
    gemm_mma_kernel<<<gblocks, 256, SMEM_A>>>(
        x, bfrag + 0 * 8192, bfrag + 1 * 8192, nullptr, f_ptr, num_atoms);

    // 2) CSR offsets
    offsets_kernel<<<(num_atoms + 1 + 255) / 256, 256>>>(seg, num_edges, num_atoms);

    // 3) conv = segment_sum(w_ij * f[idx_j])
    conv_kernel<<<(num_atoms + 3) / 4, 128>>>(wij, idxj, num_atoms);

    // 4) out = conv @ W_out + b_out
    gemm_mma_kernel<<<gblocks, 256, SMEM_A>>>(
        conv_ptr, bfrag + 2 * 8192, bfrag + 3 * 8192, bout, (float*)d_out, num_atoms);
}

// round 4
// speedup vs baseline: 1.5508x; 1.1975x over previous
#include <cuda_runtime.h>
#include <cuda_bf16.h>
#include <cstdint>

#define MAX_ATOMS 40000
#define MAX_EDGES 640000
#define NFM 128

// ---------------------------------------------------------------------------
// Scratch
// ---------------------------------------------------------------------------
__device__ float    g_f[(size_t)MAX_ATOMS * NFM];     // f = x @ W_in
__device__ float    g_conv[(size_t)MAX_ATOMS * NFM];  // segment-summed conv
__device__ int      g_rowstart[MAX_ATOMS + 1];        // CSR offsets
// Pre-packed B fragments in mma.m16n8k16 register order.
// [matrix: 0=Win 1=Wout][term: 0=hi 1=lo][ ((t*8+k)*32+lane)*2 + reg ]
__device__ uint32_t g_Bfrag[2][2][8192];

// ---------------------------------------------------------------------------
__device__ __forceinline__ void split_pair(float v0, float v1,
                                           uint32_t& hp, uint32_t& lp) {
    __nv_bfloat16 h0 = __float2bfloat16(v0);
    __nv_bfloat16 h1 = __float2bfloat16(v1);
    __nv_bfloat16 l0 = __float2bfloat16(v0 - __bfloat162float(h0));
    __nv_bfloat16 l1 = __float2bfloat16(v1 - __bfloat162float(h1));
    hp = (uint32_t)__bfloat16_as_ushort(h0) | ((uint32_t)__bfloat16_as_ushort(h1) << 16);
    lp = (uint32_t)__bfloat16_as_ushort(l0) | ((uint32_t)__bfloat16_as_ushort(l1) << 16);
}

__device__ __forceinline__ void mma16816(float* c, const uint32_t* a,
                                         uint32_t b0, uint32_t b1) {
    asm volatile(
        "mma.sync.aligned.m16n8k16.row.col.f32.bf16.bf16.f32 "
        "{%0,%1,%2,%3}, {%4,%5,%6,%7}, {%8,%9}, {%0,%1,%2,%3};"
        : "+f"(c[0]), "+f"(c[1]), "+f"(c[2]), "+f"(c[3])
        : "r"(a[0]), "r"(a[1]), "r"(a[2]), "r"(a[3]), "r"(b0), "r"(b1));
}

// ---------------------------------------------------------------------------
// Prep: pack weights into B-fragment order, split hi/lo. W is [K,N] row-major.
// ---------------------------------------------------------------------------
__global__ void prep_weights_kernel(const float* __restrict__ W_in,
                                    const float* __restrict__ W_out)
{
    int id = blockIdx.x * blockDim.x + threadIdx.x;   // 0..32767
    int reg  = id & 1;
    int lane = (id >> 1) & 31;
    int k    = (id >> 6) & 7;
    int t    = (id >> 9) & 15;
    int term = (id >> 13) & 1;
    int mat  = (id >> 14) & 1;

    const float* W = mat ? W_out : W_in;
    int kr = k * 16 + (lane & 3) * 2 + reg * 8;
    int n  = t * 8 + (lane >> 2);
    float v0 = W[(size_t)kr * 128 + n];
    float v1 = W[(size_t)(kr + 1) * 128 + n];
    uint32_t hp, lp;
    split_pair(v0, v1, hp, lp);
    g_Bfrag[mat][term][(((t * 8 + k) * 32) + lane) * 2 + reg] = term ? lp : hp;
}

// ---------------------------------------------------------------------------
// GEMM via mma.sync: C[M,128] = A[M,128] @ W[128,128] (+bias).
// Split bf16 3-term. CTA: 64x128 tile, 8 warps (warp tile 32x32), 2 CTAs/SM.
// ---------------------------------------------------------------------------
#define A_STRIDE 136   // bf16 elems per row (bank-conflict-free: 68 words, 4g+tg)

__global__ __launch_bounds__(256, 2)
void gemm_mma_kernel(const float* __restrict__ A,
                     const uint32_t* __restrict__ Bh,
                     const uint32_t* __restrict__ Bl,
                     const float* __restrict__ bias,
                     float* __restrict__ C, int M)
{
    extern __shared__ __nv_bfloat16 sA[];     // [2][64][A_STRIDE]
    __nv_bfloat16* Ah = sA;
    __nv_bfloat16* Al = sA + 64 * A_STRIDE;

    const int tid = threadIdx.x;
    const int m0  = blockIdx.x * 64;

    // ---- stage A tile: fp32 -> hi/lo bf16 in smem ----
#pragma unroll
    for (int it = 0; it < 16; it++) {
        int p  = tid + it * 256;              // 0..4095 pairs
        int m  = p >> 6;                      // local row 0..63
        int kp = (p & 63) << 1;               // even col
        float2 v = make_float2(0.f, 0.f);
        if (m0 + m < M)
            v = *reinterpret_cast<const float2*>(&A[(size_t)(m0 + m) * 128 + kp]);
        uint32_t hp, lp;
        split_pair(v.x, v.y, hp, lp);
        *reinterpret_cast<uint32_t*>(&Ah[m * A_STRIDE + kp]) = hp;
        *reinterpret_cast<uint32_t*>(&Al[m * A_STRIDE + kp]) = lp;
    }
    __syncthreads();

    const int wid  = tid >> 5;
    const int lane = tid & 31;
    const int wm   = wid & 1;                 // M slice (32 rows)
    const int wn   = wid >> 1;                // N slice (32 cols)
    const int g    = lane >> 2;               // 0..7
    const int tg   = lane & 3;                // 0..3

    float acc[2][4][4];
#pragma unroll
    for (int mf = 0; mf < 2; mf++)
#pragma unroll
        for (int t4 = 0; t4 < 4; t4++)
#pragma unroll
            for (int i = 0; i < 4; i++) acc[mf][t4][i] = 0.f;

#pragma unroll
    for (int k = 0; k < 8; k++) {
        uint32_t ah[2][4], al[2][4];
        const int cb = k * 16 + tg * 2;
#pragma unroll
        for (int mf = 0; mf < 2; mf++) {
            int r = wm * 32 + mf * 16 + g;
            ah[mf][0] = *reinterpret_cast<const uint32_t*>(&Ah[r * A_STRIDE + cb]);
            ah[mf][1] = *reinterpret_cast<const uint32_t*>(&Ah[(r + 8) * A_STRIDE + cb]);
            ah[mf][2] = *reinterpret_cast<const uint32_t*>(&Ah[r * A_STRIDE + cb + 8]);
            ah[mf][3] = *reinterpret_cast<const uint32_t*>(&Ah[(r + 8) * A_STRIDE + cb + 8]);
            al[mf][0] = *reinterpret_cast<const uint32_t*>(&Al[r * A_STRIDE + cb]);
            al[mf][1] = *reinterpret_cast<const uint32_t*>(&Al[(r + 8) * A_STRIDE + cb]);
            al[mf][2] = *reinterpret_cast<const uint32_t*>(&Al[r * A_STRIDE + cb + 8]);
            al[mf][3] = *reinterpret_cast<const uint32_t*>(&Al[(r + 8) * A_STRIDE + cb + 8]);
        }
#pragma unroll
        for (int t4 = 0; t4 < 4; t4++) {
            int fidx = (((wn * 4 + t4) * 8 + k) * 32 + lane) * 2;
            uint32_t bh0 = __ldg(&Bh[fidx]);
            uint32_t bh1 = __ldg(&Bh[fidx + 1]);
            uint32_t bl0 = __ldg(&Bl[fidx]);
            uint32_t bl1 = __ldg(&Bl[fidx + 1]);
#pragma unroll
            for (int mf = 0; mf < 2; mf++) {
                mma16816(acc[mf][t4], ah[mf], bh0, bh1);   // Ah*Bh
                mma16816(acc[mf][t4], ah[mf], bl0, bl1);   // Ah*Bl
                mma16816(acc[mf][t4], al[mf], bh0, bh1);   // Al*Bh
            }
        }
    }

    // ---- epilogue ----
#pragma unroll
    for (int t4 = 0; t4 < 4; t4++) {
        int col = wn * 32 + t4 * 8 + tg * 2;
        float b0 = bias ? __ldg(&bias[col])     : 0.f;
        float b1 = bias ? __ldg(&bias[col + 1]) : 0.f;
#pragma unroll
        for (int mf = 0; mf < 2; mf++) {
            int row = m0 + wm * 32 + mf * 16 + g;
            if (row < M) {
                float2 o0 = make_float2(acc[mf][t4][0] + b0, acc[mf][t4][1] + b1);
                *reinterpret_cast<float2*>(&C[(size_t)row * 128 + col]) = o0;
            }
            if (row + 8 < M) {
                float2 o1 = make_float2(acc[mf][t4][2] + b0, acc[mf][t4][3] + b1);
                *reinterpret_cast<float2*>(&C[(size_t)(row + 8) * 128 + col]) = o1;
            }
        }
    }
}

// ---------------------------------------------------------------------------
// CSR offsets from sorted seg_i
// ---------------------------------------------------------------------------
__global__ void offsets_kernel(const int* __restrict__ seg_i, int num_edges, int num_atoms)
{
    int a = blockIdx.x * blockDim.x + threadIdx.x;
    if (a > num_atoms) return;
    int lo = 0, hi = num_edges;
    while (lo < hi) {
        int mid = (lo + hi) >> 1;
        if (seg_i[mid] < a) lo = mid + 1; else hi = mid;
    }
    g_rowstart[a] = lo;
}

// ---------------------------------------------------------------------------
// Edge kernel: one warp per atom, lane owns 4 channels. Unroll-4 for MLP;
// w_ij streamed with evict-first (__ldcs) so the f table stays in L2.
// ---------------------------------------------------------------------------
__global__ __launch_bounds__(256)
void conv_kernel(const float* __restrict__ w_ij, const int* __restrict__ idx_j,
                 int num_atoms)
{
    const int warp = threadIdx.x >> 5;
    const int lane = threadIdx.x & 31;
    const int a = blockIdx.x * 8 + warp;
    if (a >= num_atoms) return;

    const int s = g_rowstart[a];
    const int e = g_rowstart[a + 1];
    const int c = lane * 4;

    float4 acc = make_float4(0.f, 0.f, 0.f, 0.f);

    int k = s;
    for (; k + 3 < e; k += 4) {
        int j0 = __ldg(&idx_j[k]);
        int j1 = __ldg(&idx_j[k + 1]);
        int j2 = __ldg(&idx_j[k + 2]);
        int j3 = __ldg(&idx_j[k + 3]);
        float4 w0 = __ldcs(reinterpret_cast<const float4*>(&w_ij[(size_t)k * 128 + c]));
        float4 w1 = __ldcs(reinterpret_cast<const float4*>(&w_ij[(size_t)(k + 1) * 128 + c]));
        float4 w2 = __ldcs(reinterpret_cast<const float4*>(&w_ij[(size_t)(k + 2) * 128 + c]));
        float4 w3 = __ldcs(reinterpret_cast<const float4*>(&w_ij[(size_t)(k + 3) * 128 + c]));
        float4 f0 = __ldg(reinterpret_cast<const float4*>(&g_f[(size_t)j0 * 128 + c]));
        float4 f1 = __ldg(reinterpret_cast<const float4*>(&g_f[(size_t)j1 * 128 + c]));
        float4 f2 = __ldg(reinterpret_cast<const float4*>(&g_f[(size_t)j2 * 128 + c]));
        float4 f3 = __ldg(reinterpret_cast<const float4*>(&g_f[(size_t)j3 * 128 + c]));
        acc.x = fmaf(w0.x, f0.x, acc.x); acc.y = fmaf(w0.y, f0.y, acc.y);
        acc.z = fmaf(w0.z, f0.z, acc.z); acc.w = fmaf(w0.w, f0.w, acc.w);
        acc.x = fmaf(w1.x, f1.x, acc.x); acc.y = fmaf(w1.y, f1.y, acc.y);
        acc.z = fmaf(w1.z, f1.z, acc.z); acc.w = fmaf(w1.w, f1.w, acc.w);
        acc.x = fmaf(w2.x, f2.x, acc.x); acc.y = fmaf(w2.y, f2.y, acc.y);
        acc.z = fmaf(w2.z, f2.z, acc.z); acc.w = fmaf(w2.w, f2.w, acc.w);
        acc.x = fmaf(w3.x, f3.x, acc.x); acc.y = fmaf(w3.y, f3.y, acc.y);
        acc.z = fmaf(w3.z, f3.z, acc.z); acc.w = fmaf(w3.w, f3.w, acc.w);
    }
    for (; k < e; k++) {
        int j0 = __ldg(&idx_j[k]);
        float4 w0 = __ldcs(reinterpret_cast<const float4*>(&w_ij[(size_t)k * 128 + c]));
        float4 f0 = __ldg(reinterpret_cast<const float4*>(&g_f[(size_t)j0 * 128 + c]));
        acc.x = fmaf(w0.x, f0.x, acc.x); acc.y = fmaf(w0.y, f0.y, acc.y);
        acc.z = fmaf(w0.z, f0.z, acc.z); acc.w = fmaf(w0.w, f0.w, acc.w);
    }

    *reinterpret_cast<float4*>(&g_conv[(size_t)a * 128 + c]) = acc;
}

// ---------------------------------------------------------------------------
extern "C" void kernel_launch(void* const* d_in, const int* in_sizes, int n_in,
                              void* d_out, int out_size)
{
    const float* x    = (const float*)d_in[0];
    const float* wij  = (const float*)d_in[1];
    const int*   seg  = (const int*)d_in[2];
    const int*   idxj = (const int*)d_in[3];
    int base = 4;
    if (n_in >= 8 && in_sizes[4] == 1) base = 5;   // skip scalar seg_i_sum
    const float* Win  = (const float*)d_in[base];
    const float* Wout = (const float*)d_in[base + 1];
    const float* bout = (const float*)d_in[base + 2];

    int num_edges = in_sizes[2];
    int num_atoms = out_size / NFM;
    if (num_atoms > MAX_ATOMS) num_atoms = MAX_ATOMS;
    if (num_edges > MAX_EDGES) num_edges = MAX_EDGES;

    float*    f_ptr    = nullptr;
    float*    conv_ptr = nullptr;
    uint32_t* bfrag    = nullptr;
    cudaGetSymbolAddress((void**)&f_ptr, g_f);
    cudaGetSymbolAddress((void**)&conv_ptr, g_conv);
    cudaGetSymbolAddress((void**)&bfrag, g_Bfrag);

    const int SMEM_A = 2 * 64 * A_STRIDE * (int)sizeof(__nv_bfloat16);  // 34816
    cudaFuncSetAttribute(gemm_mma_kernel,
                         cudaFuncAttributeMaxDynamicSharedMemorySize, SMEM_A);

    int gblocks = (num_atoms + 63) / 64;

    // 0) pack weights into mma B fragments (hi/lo)
    prep_weights_kernel<<<128, 256>>>(Win, Wout);

    // 1) f = x @ W_in
    gemm_mma_kernel<<<gblocks, 256, SMEM_A>>>(
        x, bfrag + 0 * 8192, bfrag + 1 * 8192, nullptr, f_ptr, num_atoms);

    // 2) CSR offsets
    offsets_kernel<<<(num_atoms + 1 + 255) / 256, 256>>>(seg, num_edges, num_atoms);

    // 3) conv = segment_sum(w_ij * f[idx_j])
    conv_kernel<<<(num_atoms + 7) / 8, 256>>>(wij, idxj, num_atoms);

    // 4) out = conv @ W_out + b_out
    gemm_mma_kernel<<<gblocks, 256, SMEM_A>>>(
        conv_ptr, bfrag + 2 * 8192, bfrag + 3 * 8192, bout, (float*)d_out, num_atoms);
}